// round 6
// baseline (speedup 1.0000x reference)
#include <cuda_runtime.h>
#include <cuda_bf16.h>

// Problem constants
#define B_DIM 16
#define T_DIM 100
#define FRAME_INTS 3888         // 27*48*3
#define NBINS 512
#define WIN 101
#define HALF 50
#define ODIM 128

#define NBLK 148                // <= SM count (B300:148, GB300:152); 1 block/SM resident
#define NTHR 512

// Scratch (device globals — no allocation allowed)
__device__ float g_hist[B_DIM * T_DIM * NBINS];   // 3.28 MB
__device__ float g_sim [B_DIM * T_DIM * T_DIM];   // 640 KB

// Grid-wide barrier state (self-resetting, sense-reversing)
__device__ int          g_cnt[2];     // zero-initialized
__device__ volatile int g_sense[2];

// ---- f32x2 packed-FMA helpers (FFMA2) --------------------------------------
__device__ __forceinline__ void ffma2(unsigned long long& d,
                                      unsigned long long a,
                                      unsigned long long b) {
    asm("fma.rn.f32x2 %0, %1, %2, %0;" : "+l"(d) : "l"(a), "l"(b));
}
__device__ __forceinline__ float2 f2unpack(unsigned long long u) {
    float2 f;
    asm("mov.b64 {%0, %1}, %2;" : "=f"(f.x), "=f"(f.y) : "l"(u));
    return f;
}
__device__ __forceinline__ unsigned long long f2pack(float a, float b) {
    unsigned long long u;
    asm("mov.b64 %0, {%1, %2};" : "=l"(u) : "f"(a), "f"(b));
    return u;
}

// ---- device-wide barrier (all NBLK blocks resident by construction) --------
__device__ __forceinline__ void gbar(int idx) {
    __syncthreads();
    if (threadIdx.x == 0) {
        volatile int* sense = &g_sense[idx];
        int s = *sense;
        __threadfence();
        if (atomicAdd(&g_cnt[idx], 1) == NBLK - 1) {
            g_cnt[idx] = 0;
            __threadfence();
            *sense = 1 - s;
        } else {
            while (*sense == s) { }
            __threadfence();
        }
    }
    __syncthreads();
}

// sim tile table: ti<=tj (symmetry), |ti-tj|==3 skipped (outside +-50 band)
__constant__ int c_ti[9] = {0,0,0,1,1,1,2,2,3};
__constant__ int c_tj[9] = {0,1,2,1,2,3,2,3,3};

#define AS_STRIDE 516
#define SIM_SMEM_FLOATS (2*32*AS_STRIDE + 4*32*36)      // 37632 floats
#define SMEM_BYTES (SIM_SMEM_FLOATS * 4)                // 150528 B (max over phases)

__global__ __launch_bounds__(NTHR, 1)
void k_all(const int* __restrict__ frames,
           const float* __restrict__ fc_w,
           const float* __restrict__ fc_b,
           float* __restrict__ out) {
    extern __shared__ __align__(16) float sm[];
    const int tid = threadIdx.x;

    // ========================= Phase 1: histograms ==========================
    // 2 frames per iteration; 800 pair-tasks strided over 148 blocks.
    {
        int* sh = (int*)sm;                 // [2][512]
        __shared__ int   wsum[2][16];
        __shared__ float sinv[2];

        for (int p = blockIdx.x; p < 800; p += NBLK) {
            const long long f0 = 2LL * p;

            sh[tid]       = 0;
            sh[tid + 512] = 0;
            __syncthreads();

            const int4* base = reinterpret_cast<const int4*>(frames + f0 * FRAME_INTS);
            for (int c = tid; c < 648; c += NTHR) {
                int fr = (c >= 324);
                int cc = c - 324 * fr;
                const int4* bp = base + fr * 972 + 3 * cc;
                int4 a = bp[0], b = bp[1], d = bp[2];
                int off = fr << 9;
                atomicAdd(&sh[off + (((a.x >> 5) << 6) | ((a.y >> 5) << 3) | (a.z >> 5))], 1);
                atomicAdd(&sh[off + (((a.w >> 5) << 6) | ((b.x >> 5) << 3) | (b.y >> 5))], 1);
                atomicAdd(&sh[off + (((b.z >> 5) << 6) | ((b.w >> 5) << 3) | (d.x >> 5))], 1);
                atomicAdd(&sh[off + (((d.y >> 5) << 6) | ((d.z >> 5) << 3) | (d.w >> 5))], 1);
            }
            __syncthreads();

            int v0 = sh[tid];
            int v1 = sh[512 + tid];
            int s0 = v0 * v0, s1 = v1 * v1;
            #pragma unroll
            for (int o = 16; o; o >>= 1) {
                s0 += __shfl_down_sync(0xffffffff, s0, o);
                s1 += __shfl_down_sync(0xffffffff, s1, o);
            }
            if ((tid & 31) == 0) { wsum[0][tid >> 5] = s0; wsum[1][tid >> 5] = s1; }
            __syncthreads();
            if (tid < 2) {
                int tot = 0;
                #pragma unroll
                for (int w = 0; w < 16; w++) tot += wsum[tid][w];
                sinv[tid] = 1.0f / sqrtf((float)tot);
            }
            __syncthreads();

            g_hist[f0 * NBINS + tid]           = (float)v0 * sinv[0];
            g_hist[(f0 + 1) * NBINS + tid]     = (float)v1 * sinv[1];
            __syncthreads();   // protect sh / sinv before next iteration
        }
    }

    gbar(0);

    // ========================= Phase 2: sim = X X^T =========================
    // 144 tile-tasks (<=1 per block). 16 warps = 4 k-quarters x 4 col-groups.
    if (blockIdx.x < 144) {
        const int task = blockIdx.x;
        const int b  = task / 9;
        const int tl = task % 9;
        const int ti = c_ti[tl], tj = c_tj[tl];
        const bool diag = (ti == tj);

        float* A_s = sm;                          // [32][516]
        float* B_s = sm + 32 * AS_STRIDE;         // [32][516]
        float* red = sm + 64 * AS_STRIDE;         // [4][32][36]

        const int row0 = ti * 32;
        const int col0 = tj * 32;
        const float* X = g_hist + (long long)b * T_DIM * NBINS;

        for (int i = tid; i < 4096; i += NTHR) {
            int row = i >> 7;
            int k   = (i & 127) << 2;
            int gr = min(row0 + row, T_DIM - 1);
            float4 va = *reinterpret_cast<const float4*>(X + gr * NBINS + k);
            *reinterpret_cast<float4*>(A_s + row * AS_STRIDE + k) = va;
            if (!diag) {
                int gc = min(col0 + row, T_DIM - 1);
                float4 vb = *reinterpret_cast<const float4*>(X + gc * NBINS + k);
                *reinterpret_cast<float4*>(B_s + row * AS_STRIDE + k) = vb;
            }
        }
        __syncthreads();

        const float* Bp = diag ? A_s : B_s;
        const int w    = tid >> 5;
        const int lane = tid & 31;
        const int q    = w >> 2;
        const int wc   = w & 3;
        const int r0   = lane & 15;
        const int rh   = lane >> 4;
        const int cb   = 8 * wc + 4 * rh;
        const int kb   = 128 * q;

        unsigned long long acc[8];
        #pragma unroll
        for (int i = 0; i < 8; i++) acc[i] = 0ull;

        const float* a0 = A_s + r0 * AS_STRIDE + kb;
        const float* a1 = a0 + 16 * AS_STRIDE;
        const float* b0 = Bp + (cb + 0) * AS_STRIDE + kb;
        const float* b1 = b0 + AS_STRIDE;
        const float* b2 = b1 + AS_STRIDE;
        const float* b3 = b2 + AS_STRIDE;

        #pragma unroll 4
        for (int k = 0; k < 128; k += 4) {
            ulonglong2 aL = *reinterpret_cast<const ulonglong2*>(a0 + k);
            ulonglong2 aH = *reinterpret_cast<const ulonglong2*>(a1 + k);
            ulonglong2 q0 = *reinterpret_cast<const ulonglong2*>(b0 + k);
            ulonglong2 q1 = *reinterpret_cast<const ulonglong2*>(b1 + k);
            ulonglong2 q2 = *reinterpret_cast<const ulonglong2*>(b2 + k);
            ulonglong2 q3 = *reinterpret_cast<const ulonglong2*>(b3 + k);

            ffma2(acc[0], aL.x, q0.x); ffma2(acc[0], aL.y, q0.y);
            ffma2(acc[1], aL.x, q1.x); ffma2(acc[1], aL.y, q1.y);
            ffma2(acc[2], aL.x, q2.x); ffma2(acc[2], aL.y, q2.y);
            ffma2(acc[3], aL.x, q3.x); ffma2(acc[3], aL.y, q3.y);
            ffma2(acc[4], aH.x, q0.x); ffma2(acc[4], aH.y, q0.y);
            ffma2(acc[5], aH.x, q1.x); ffma2(acc[5], aH.y, q1.y);
            ffma2(acc[6], aH.x, q2.x); ffma2(acc[6], aH.y, q2.y);
            ffma2(acc[7], aH.x, q3.x); ffma2(acc[7], aH.y, q3.y);
        }

        #pragma unroll
        for (int rr = 0; rr < 2; rr++) {
            #pragma unroll
            for (int cc = 0; cc < 4; cc++) {
                float2 f = f2unpack(acc[rr * 4 + cc]);
                red[(q * 32 + r0 + 16 * rr) * 36 + cb + cc] = f.x + f.y;
            }
        }
        __syncthreads();

        float* S = g_sim + (long long)b * T_DIM * T_DIM;
        #pragma unroll
        for (int j = 0; j < 2; j++) {
            int o = tid + j * NTHR;
            int r = o >> 5, c = o & 31;
            float v = red[(r     ) * 36 + c] + red[(32 + r) * 36 + c]
                    + red[(64 + r) * 36 + c] + red[(96 + r) * 36 + c];
            int gr = row0 + r, gc = col0 + c;
            if (gr < T_DIM && gc < T_DIM) {
                S[gr * T_DIM + gc] = v;
                S[gc * T_DIM + gr] = v;
            }
        }
    }

    gbar(1);

    // ========================= Phase 3: band + FC + ReLU ====================
    // 160 tasks over 148 blocks. 512 threads = (d in 128) x (q = s-quarter).
    {
        float* W    = sm;                        // [101][128]
        float* band = sm + WIN * ODIM;           // [101][16] (t 0..9 used)
        float* scr  = sm + WIN * ODIM + 101*16;  // [3][10][128]

        for (int task = blockIdx.x; task < 160; task += NBLK) {
            const int b  = task / 10;
            const int t0 = (task % 10) * 10;

            {
                const float4* src = reinterpret_cast<const float4*>(fc_w);
                float4* dst = reinterpret_cast<float4*>(W);
                for (int i = tid; i < (WIN * ODIM) / 4; i += NTHR) dst[i] = src[i];
            }
            const float* S = g_sim + (long long)b * T_DIM * T_DIM;
            for (int i = tid; i < 10 * WIN; i += NTHR) {
                int tt = i / WIN, s = i - tt * WIN;
                int t  = t0 + tt;
                int t2 = t + s - HALF;
                band[s * 16 + tt] = (t2 >= 0 && t2 < T_DIM) ? S[t * T_DIM + t2] : 0.f;
            }
            __syncthreads();

            const int d = tid & 127;
            const int q = tid >> 7;
            const int s0 = q * 26;
            const int s1 = min(WIN, s0 + 26);

            unsigned long long acc2[5];
            #pragma unroll
            for (int i = 0; i < 5; i++) acc2[i] = 0ull;

            for (int s = s0; s < s1; s++) {
                float wv = W[s * ODIM + d];
                unsigned long long ww = f2pack(wv, wv);
                const float* bt = band + s * 16;
                ulonglong2 p01 = *reinterpret_cast<const ulonglong2*>(bt);
                ulonglong2 p23 = *reinterpret_cast<const ulonglong2*>(bt + 4);
                unsigned long long p4 = *reinterpret_cast<const unsigned long long*>(bt + 8);
                ffma2(acc2[0], ww, p01.x);
                ffma2(acc2[1], ww, p01.y);
                ffma2(acc2[2], ww, p23.x);
                ffma2(acc2[3], ww, p23.y);
                ffma2(acc2[4], ww, p4);
            }

            float acc[10];
            #pragma unroll
            for (int p = 0; p < 5; p++) {
                float2 f = f2unpack(acc2[p]);
                acc[2 * p]     = f.x;
                acc[2 * p + 1] = f.y;
            }

            if (q) {
                float* sc = scr + (q - 1) * (10 * ODIM);
                #pragma unroll
                for (int tt = 0; tt < 10; tt++) sc[tt * ODIM + d] = acc[tt];
            }
            __syncthreads();

            if (q == 0) {
                const float bias = fc_b[d];
                float* O = out + ((long long)(b * T_DIM + t0)) * ODIM + d;
                #pragma unroll
                for (int tt = 0; tt < 10; tt++) {
                    float v = acc[tt] + bias
                            + scr[0 * (10*ODIM) + tt * ODIM + d]
                            + scr[1 * (10*ODIM) + tt * ODIM + d]
                            + scr[2 * (10*ODIM) + tt * ODIM + d];
                    O[tt * ODIM] = fmaxf(v, 0.f);
                }
            }
            __syncthreads();   // smem reused by next task
        }
    }
}

// ---------------------------------------------------------------------------
extern "C" void kernel_launch(void* const* d_in, const int* in_sizes, int n_in,
                              void* d_out, int out_size) {
    const int*   frames = (const int*)  d_in[0];
    const float* fc_w   = (const float*)d_in[1];
    const float* fc_b   = (const float*)d_in[2];
    float*       out    = (float*)d_out;

    cudaFuncSetAttribute(k_all, cudaFuncAttributeMaxDynamicSharedMemorySize,
                         SMEM_BYTES);
    k_all<<<NBLK, NTHR, SMEM_BYTES>>>(frames, fc_w, fc_b, out);
}

// round 7
// speedup vs baseline: 1.1790x; 1.1790x over previous
#include <cuda_runtime.h>
#include <cuda_bf16.h>

// Problem constants
#define B_DIM 16
#define T_DIM 100
#define FRAME_INTS 3888         // 27*48*3
#define NBINS 512
#define WIN 101
#define HALF 50
#define ODIM 128

// Scratch (device globals — no allocation allowed)
__device__ float g_hist[B_DIM * T_DIM * NBINS];   // 3.28 MB
__device__ float g_sim [B_DIM * T_DIM * T_DIM];   // 640 KB

// ---- f32x2 packed-FMA helpers (FFMA2) --------------------------------------
__device__ __forceinline__ void ffma2(unsigned long long& d,
                                      unsigned long long a,
                                      unsigned long long b) {
    asm("fma.rn.f32x2 %0, %1, %2, %0;" : "+l"(d) : "l"(a), "l"(b));
}
__device__ __forceinline__ float2 f2unpack(unsigned long long u) {
    float2 f;
    asm("mov.b64 {%0, %1}, %2;" : "=f"(f.x), "=f"(f.y) : "l"(u));
    return f;
}
__device__ __forceinline__ unsigned long long f2pack(float a, float b) {
    unsigned long long u;
    asm("mov.b64 %0, {%1, %2};" : "=l"(u) : "f"(a), "f"(b));
    return u;
}

// ---------------------------------------------------------------------------
// Kernel 1: histograms. 400 blocks x 512 threads, 4 frames per block.
// Front-batched streaming loads (up to 9 LDG.128 in flight per thread before
// any atomic), 4 private smem histograms.
// ---------------------------------------------------------------------------
__global__ __launch_bounds__(512) void k_hist(const int* __restrict__ frames,
                                              float* __restrict__ hist) {
    __shared__ int sh[4][NBINS];          // 8 KB
    __shared__ int wsum[4][4];
    __shared__ float sinv[4];

    const int tid = threadIdx.x;
    const long long f0 = 4LL * blockIdx.x;

    #pragma unroll
    for (int i = 0; i < 4; i++) sh[i][tid & 511] = 0;   // tid<512 covers all
    __syncthreads();

    const int4* base = reinterpret_cast<const int4*>(frames + f0 * FRAME_INTS);

    // 1296 chunks (4 frames x 324); thread handles tid, tid+512, tid+1024.
    int4 v[3][3];
    int  fr[3];
    int  nj = 0;
    #pragma unroll
    for (int j = 0; j < 3; j++) {
        int c = tid + j * 512;
        if (c < 1296) {
            int f  = c / 324;
            int cc = c - f * 324;
            const int4* bp = base + f * 972 + 3 * cc;
            v[j][0] = __ldcs(bp + 0);
            v[j][1] = __ldcs(bp + 1);
            v[j][2] = __ldcs(bp + 2);
            fr[j] = f;
            nj = j + 1;
        }
    }

    #pragma unroll
    for (int j = 0; j < 3; j++) {
        if (j < nj) {
            int* h = sh[fr[j]];
            int4 a = v[j][0], b = v[j][1], d = v[j][2];
            atomicAdd(&h[((a.x >> 5) << 6) | ((a.y >> 5) << 3) | (a.z >> 5)], 1);
            atomicAdd(&h[((a.w >> 5) << 6) | ((b.x >> 5) << 3) | (b.y >> 5)], 1);
            atomicAdd(&h[((b.z >> 5) << 6) | ((b.w >> 5) << 3) | (d.x >> 5)], 1);
            atomicAdd(&h[((d.y >> 5) << 6) | ((d.z >> 5) << 3) | (d.w >> 5)], 1);
        }
    }
    __syncthreads();

    // Sum of squares per frame: 128-thread group per frame (4 bins each).
    const int g   = tid >> 7;        // frame within block
    const int gl  = tid & 127;
    int h0 = sh[g][gl];
    int h1 = sh[g][gl + 128];
    int h2 = sh[g][gl + 256];
    int h3 = sh[g][gl + 384];
    int s = h0*h0 + h1*h1 + h2*h2 + h3*h3;
    #pragma unroll
    for (int o = 16; o; o >>= 1) s += __shfl_down_sync(0xffffffff, s, o);
    if ((gl & 31) == 0) wsum[g][gl >> 5] = s;
    __syncthreads();
    if (tid < 4) {
        int tot = wsum[tid][0] + wsum[tid][1] + wsum[tid][2] + wsum[tid][3];
        sinv[tid] = 1.0f / sqrtf((float)tot);
    }
    __syncthreads();

    const float inv = sinv[g];
    float* out = hist + (f0 + g) * NBINS;
    out[gl      ] = (float)h0 * inv;
    out[gl + 128] = (float)h1 * inv;
    out[gl + 256] = (float)h2 * inv;
    out[gl + 384] = (float)h3 * inv;
}

// ---------------------------------------------------------------------------
// Kernel 2: sim[b] = X[b] @ X[b]^T, banded + symmetric.
// Fully smem-resident 32x32x512 tile. 512 threads, 2 barriers.
// 16 warps = 4 k-quarters x 4 col-groups. FFMA2 with accumulator
// interleaving (dep distance 8 instructions). Diag tiles alias A==B.
// ---------------------------------------------------------------------------
__constant__ int c_ti[9] = {0,0,0,1,1,1,2,2,3};
__constant__ int c_tj[9] = {0,1,2,1,2,3,2,3,3};

#define AS_STRIDE 516
#define SIM_SMEM_FLOATS (2*32*AS_STRIDE + 4*32*36)
#define SIM_SMEM_BYTES  (SIM_SMEM_FLOATS * 4)   // 150528

__global__ __launch_bounds__(512) void k_sim(const float* __restrict__ hist,
                                             float* __restrict__ sim) {
    extern __shared__ __align__(16) float sm[];
    float* A_s = sm;                          // [32][516]
    float* B_s = sm + 32 * AS_STRIDE;         // [32][516]
    float* red = sm + 64 * AS_STRIDE;         // [4][32][36]

    const int b  = blockIdx.y;
    const int tl = blockIdx.x;
    const int ti = c_ti[tl], tj = c_tj[tl];
    const bool diag = (ti == tj);

    const int row0 = ti * 32;
    const int col0 = tj * 32;
    const float* X = hist + (long long)b * T_DIM * NBINS;
    const int tid = threadIdx.x;

    for (int i = tid; i < 4096; i += 512) {
        int row = i >> 7;
        int k   = (i & 127) << 2;
        int gr = min(row0 + row, T_DIM - 1);   // clamp: excess rows masked at write
        float4 va = *reinterpret_cast<const float4*>(X + gr * NBINS + k);
        *reinterpret_cast<float4*>(A_s + row * AS_STRIDE + k) = va;
        if (!diag) {
            int gc = min(col0 + row, T_DIM - 1);
            float4 vb = *reinterpret_cast<const float4*>(X + gc * NBINS + k);
            *reinterpret_cast<float4*>(B_s + row * AS_STRIDE + k) = vb;
        }
    }
    __syncthreads();

    const float* Bp = diag ? A_s : B_s;
    const int w    = tid >> 5;
    const int lane = tid & 31;
    const int q    = w >> 2;          // k-quarter
    const int wc   = w & 3;           // col-group
    const int r0   = lane & 15;       // rows r0, r0+16
    const int rh   = lane >> 4;
    const int cb   = 8 * wc + 4 * rh; // cols cb..cb+3
    const int kb   = 128 * q;

    unsigned long long acc[8];
    #pragma unroll
    for (int i = 0; i < 8; i++) acc[i] = 0ull;

    const float* a0 = A_s + r0 * AS_STRIDE + kb;
    const float* a1 = a0 + 16 * AS_STRIDE;
    const float* b0 = Bp + (cb + 0) * AS_STRIDE + kb;
    const float* b1 = b0 + AS_STRIDE;
    const float* b2 = b1 + AS_STRIDE;
    const float* b3 = b2 + AS_STRIDE;

    #pragma unroll 4
    for (int k = 0; k < 128; k += 4) {
        ulonglong2 aL = *reinterpret_cast<const ulonglong2*>(a0 + k);
        ulonglong2 aH = *reinterpret_cast<const ulonglong2*>(a1 + k);
        ulonglong2 q0 = *reinterpret_cast<const ulonglong2*>(b0 + k);
        ulonglong2 q1 = *reinterpret_cast<const ulonglong2*>(b1 + k);
        ulonglong2 q2 = *reinterpret_cast<const ulonglong2*>(b2 + k);
        ulonglong2 q3 = *reinterpret_cast<const ulonglong2*>(b3 + k);

        // Interleaved: each accumulator touched once per 8 instructions
        ffma2(acc[0], aL.x, q0.x);
        ffma2(acc[1], aL.x, q1.x);
        ffma2(acc[2], aL.x, q2.x);
        ffma2(acc[3], aL.x, q3.x);
        ffma2(acc[4], aH.x, q0.x);
        ffma2(acc[5], aH.x, q1.x);
        ffma2(acc[6], aH.x, q2.x);
        ffma2(acc[7], aH.x, q3.x);
        ffma2(acc[0], aL.y, q0.y);
        ffma2(acc[1], aL.y, q1.y);
        ffma2(acc[2], aL.y, q2.y);
        ffma2(acc[3], aL.y, q3.y);
        ffma2(acc[4], aH.y, q0.y);
        ffma2(acc[5], aH.y, q1.y);
        ffma2(acc[6], aH.y, q2.y);
        ffma2(acc[7], aH.y, q3.y);
    }

    #pragma unroll
    for (int rr = 0; rr < 2; rr++) {
        #pragma unroll
        for (int cc = 0; cc < 4; cc++) {
            float2 f = f2unpack(acc[rr * 4 + cc]);
            red[(q * 32 + r0 + 16 * rr) * 36 + cb + cc] = f.x + f.y;
        }
    }
    __syncthreads();

    float* S = sim + (long long)b * T_DIM * T_DIM;
    #pragma unroll
    for (int j = 0; j < 2; j++) {
        int o = tid + j * 512;
        int r = o >> 5, c = o & 31;
        float v = red[(r     ) * 36 + c] + red[(32 + r) * 36 + c]
                + red[(64 + r) * 36 + c] + red[(96 + r) * 36 + c];
        int gr = row0 + r, gc = col0 + c;
        if (gr < T_DIM && gc < T_DIM) {
            S[gr * T_DIM + gc] = v;
            S[gc * T_DIM + gr] = v;
        }
    }
}

// ---------------------------------------------------------------------------
// Kernel 3: band extraction + FC + ReLU.
// 256 threads: tid = d + 128*h; h=0 s in [0,52), h=1 s in [52,101).
// Band stored transposed [s][tt] -> per j: 3 vector broadcasts + 5 FFMA2.
// ---------------------------------------------------------------------------
#define FC_W_FLOATS  (WIN * ODIM)             // 12928
#define FC_BT_OFF    FC_W_FLOATS              // band_t [104][12]
#define FC_SCR_OFF   (FC_W_FLOATS + 104 * 12)
#define FC_SMEM_FLOATS (FC_SCR_OFF + 10 * ODIM)
#define FC_SMEM_BYTES  (FC_SMEM_FLOATS * 4)

__global__ __launch_bounds__(256) void k_fc(const float* __restrict__ sim,
                                            const float* __restrict__ fc_w,
                                            const float* __restrict__ fc_b,
                                            float* __restrict__ out) {
    extern __shared__ __align__(16) float dyn[];
    float* w_s    = dyn;                 // [101][128]
    float* band_t = dyn + FC_BT_OFF;     // [s][12] (tt 0..9 used)
    float* scr    = dyn + FC_SCR_OFF;    // [10][128]

    const int b   = blockIdx.y;
    const int t0  = blockIdx.x * 10;
    const int tid = threadIdx.x;
    const int d   = tid & 127;
    const int h   = tid >> 7;

    {
        const float4* src = reinterpret_cast<const float4*>(fc_w);
        float4* dst = reinterpret_cast<float4*>(w_s);
        for (int i = tid; i < FC_W_FLOATS / 4; i += 256) dst[i] = src[i];
    }

    const float* S = sim + (long long)b * T_DIM * T_DIM;
    for (int i = tid; i < 10 * WIN; i += 256) {
        int tt = i / WIN, s = i - tt * WIN;
        int t  = t0 + tt;
        int t2 = t + s - HALF;
        band_t[s * 12 + tt] = (t2 >= 0 && t2 < T_DIM) ? S[t * T_DIM + t2] : 0.f;
    }
    __syncthreads();

    const int s0 = h ? 52 : 0;
    const int ns = h ? 49 : 52;

    unsigned long long acc2[5];
    #pragma unroll
    for (int i = 0; i < 5; i++) acc2[i] = 0ull;

    const float* wp = w_s + d;
    for (int j = 0; j < ns; j++) {
        const int s = s0 + j;
        float wv = wp[s * ODIM];
        unsigned long long ww = f2pack(wv, wv);
        const float* bt = band_t + s * 12;
        ulonglong2 p01 = *reinterpret_cast<const ulonglong2*>(bt);
        ulonglong2 p23 = *reinterpret_cast<const ulonglong2*>(bt + 4);
        unsigned long long p4 = *reinterpret_cast<const unsigned long long*>(bt + 8);
        ffma2(acc2[0], ww, p01.x);
        ffma2(acc2[1], ww, p01.y);
        ffma2(acc2[2], ww, p23.x);
        ffma2(acc2[3], ww, p23.y);
        ffma2(acc2[4], ww, p4);
    }

    float acc[10];
    #pragma unroll
    for (int p = 0; p < 5; p++) {
        float2 f = f2unpack(acc2[p]);
        acc[2 * p]     = f.x;
        acc[2 * p + 1] = f.y;
    }

    if (h == 1) {
        #pragma unroll
        for (int tt = 0; tt < 10; tt++) scr[tt * ODIM + d] = acc[tt];
    }
    __syncthreads();

    if (h == 0) {
        const float bias = fc_b[d];
        float* O = out + ((long long)(b * T_DIM + t0)) * ODIM + d;
        #pragma unroll
        for (int tt = 0; tt < 10; tt++) {
            float v = acc[tt] + scr[tt * ODIM + d] + bias;
            O[tt * ODIM] = fmaxf(v, 0.f);
        }
    }
}

// ---------------------------------------------------------------------------
extern "C" void kernel_launch(void* const* d_in, const int* in_sizes, int n_in,
                              void* d_out, int out_size) {
    const int*   frames = (const int*)  d_in[0];
    const float* fc_w   = (const float*)d_in[1];
    const float* fc_b   = (const float*)d_in[2];
    float*       out    = (float*)d_out;

    float* hist;
    float* sim;
    cudaGetSymbolAddress((void**)&hist, g_hist);
    cudaGetSymbolAddress((void**)&sim,  g_sim);

    cudaFuncSetAttribute(k_sim, cudaFuncAttributeMaxDynamicSharedMemorySize,
                         SIM_SMEM_BYTES);
    cudaFuncSetAttribute(k_fc, cudaFuncAttributeMaxDynamicSharedMemorySize,
                         FC_SMEM_BYTES);

    k_hist<<<400, 512>>>(frames, hist);
    k_sim <<<dim3(9, B_DIM), 512, SIM_SMEM_BYTES>>>(hist, sim);
    k_fc  <<<dim3(T_DIM / 10, B_DIM), 256, FC_SMEM_BYTES>>>(sim, fc_w, fc_b, out);
}